// round 1
// baseline (speedup 1.0000x reference)
#include <cuda_runtime.h>

// Problem constants
// B=64, H=64, W=64, n=256, NF=2n+1=513, L=63*63=3969, alpha^2=25

__device__ float g_state[64 * 64 * 64 * 256];   // [cell=(i*64+j)][b][n]  256 MB
__device__ float g_HtH[64 * 513 * 520];         // upper triangle valid, ld=520
__device__ float g_HtU[64 * 513];
__device__ float g_A[64 * 513 * 520];           // augmented [513 x 514] per batch, ld=520

// ---------------------------------------------------------------------------
// Phase 1: wavefront scan.  One launch per anti-diagonal d = i+j.
// Block: 256 threads, computes 32 batches x 128 output features for one cell.
// grid = (n_cells, 2 /*batch half*/, 2 /*n half*/)
// ---------------------------------------------------------------------------
__global__ __launch_bounds__(256) void scan_diag(
    const float* __restrict__ x, const float* __restrict__ Win,
    const float* __restrict__ W1, const float* __restrict__ W2,
    int d, int i_min)
{
    __shared__ float in_s[32][36];    // [b_local][k_local(32)] padded
    __shared__ float w_s[32][128];    // [k_local][n_local]

    const int i = i_min + (int)blockIdx.x;
    const int j = d - i;
    const int b0 = (int)blockIdx.y * 32;
    const int n0 = (int)blockIdx.z * 128;
    const int tid = (int)threadIdx.x;
    const int tx = tid & 31;    // n: 4 cols each
    const int ty = tid >> 5;    // b: 4 rows each

    const bool hasL = (j > 0);
    const bool hasU = (i > 0);
    const int cellL = hasL ? ((i * 64 + (j - 1)) * 64) : 0;
    const int cellU = hasU ? (((i - 1) * 64 + j) * 64) : 0;

    float acc[4][4];
#pragma unroll
    for (int a = 0; a < 4; ++a)
#pragma unroll
        for (int c = 0; c < 4; ++c) acc[a][c] = 0.f;

    const int bb = tid >> 3;   // 0..31 (batch row for input load)
    const int kq = tid & 7;    // 0..7  (float4 index within 32-k chunk)

    for (int kc = 0; kc < 16; ++kc) {
        const int k0 = kc * 32;
        const bool isLeft = (k0 < 256);
        const bool has = isLeft ? hasL : hasU;
        const int ks = isLeft ? k0 : (k0 - 256);

        __syncthreads();
        // load 32 batches x 32 k of the concatenated [left|up] input
        {
            float4 v = make_float4(0.f, 0.f, 0.f, 0.f);
            if (has) {
                const int cell = isLeft ? cellL : cellU;
                v = *(const float4*)&g_state[(cell + b0 + bb) * 256 + ks + kq * 4];
            }
            *(float4*)&in_s[bb][kq * 4] = v;
        }
        // load W chunk: rows ks..ks+31, cols n0..n0+127
        {
            const float* __restrict__ Wm = isLeft ? W1 : W2;
#pragma unroll
            for (int t = 0; t < 4; ++t) {
                int fi = tid + t * 256;
                int kl = fi >> 5;
                int cq = fi & 31;
                *(float4*)&w_s[kl][cq * 4] =
                    *(const float4*)&Wm[(ks + kl) * 256 + n0 + cq * 4];
            }
        }
        __syncthreads();

#pragma unroll 8
        for (int kl = 0; kl < 32; ++kl) {
            float a0 = in_s[ty * 4 + 0][kl];
            float a1 = in_s[ty * 4 + 1][kl];
            float a2 = in_s[ty * 4 + 2][kl];
            float a3 = in_s[ty * 4 + 3][kl];
            float4 w = *(float4*)&w_s[kl][tx * 4];
            acc[0][0] += a0 * w.x; acc[0][1] += a0 * w.y; acc[0][2] += a0 * w.z; acc[0][3] += a0 * w.w;
            acc[1][0] += a1 * w.x; acc[1][1] += a1 * w.y; acc[1][2] += a1 * w.z; acc[1][3] += a1 * w.w;
            acc[2][0] += a2 * w.x; acc[2][1] += a2 * w.y; acc[2][2] += a2 * w.z; acc[2][3] += a2 * w.w;
            acc[3][0] += a3 * w.x; acc[3][1] += a3 * w.y; acc[3][2] += a3 * w.z; acc[3][3] += a3 * w.w;
        }
    }

    // epilogue: + x*Win, tanh, store
    const int cell = (i * 64 + j) * 64;
    float4 wv = *(const float4*)&Win[n0 + tx * 4];
#pragma unroll
    for (int bi = 0; bi < 4; ++bi) {
        int b = b0 + ty * 4 + bi;
        float xv = x[(b * 64 + i) * 64 + j];
        float4 o;
        o.x = tanhf(acc[bi][0] + xv * wv.x);
        o.y = tanhf(acc[bi][1] + xv * wv.y);
        o.z = tanhf(acc[bi][2] + xv * wv.z);
        o.w = tanhf(acc[bi][3] + xv * wv.w);
        *(float4*)&g_state[(cell + b) * 256 + n0 + tx * 4] = o;
    }
}

// ---------------------------------------------------------------------------
// Phase 2a: HtH = Haug^T Haug (513x513 per batch), upper-triangle tiles only.
// Haug column d: d<256 -> state[r+1][c][b][d]; d<512 -> state[r][c+1][b][d-256];
// d==512 -> 1.   l = r*63 + c, r,c in [0,63).
// grid = (45 tile-pairs, 64 batches), 256 threads, 64x64 tile, 4x4 per thread.
// ---------------------------------------------------------------------------
__device__ __forceinline__ float loadH(int b, int l, int col) {
    if (l >= 3969) return 0.f;
    int r = l / 63;
    int c = l - r * 63;
    if (col < 256)
        return g_state[(((r + 1) * 64 + c) * 64 + b) * 256 + col];
    else if (col < 512)
        return g_state[((r * 64 + (c + 1)) * 64 + b) * 256 + (col - 256)];
    else
        return (col == 512) ? 1.f : 0.f;
}

__global__ __launch_bounds__(256) void hth_kernel()
{
    __shared__ float Hd[32][64];
    __shared__ float He[32][64];

    int rem = (int)blockIdx.x;
    int ti = 0;
    while (rem >= 9 - ti) { rem -= 9 - ti; ++ti; }
    const int tj = ti + rem;
    const int b = (int)blockIdx.y;
    const int d0 = ti * 64, e0 = tj * 64;

    const int tid = (int)threadIdx.x;
    const int tx = tid & 15, ty = tid >> 4;
    const int dd = tid & 63, kb = tid >> 6;

    float acc[4][4];
#pragma unroll
    for (int a = 0; a < 4; ++a)
#pragma unroll
        for (int c = 0; c < 4; ++c) acc[a][c] = 0.f;

    for (int l0 = 0; l0 < 3969; l0 += 32) {
        __syncthreads();
#pragma unroll
        for (int t = 0; t < 8; ++t) {
            int kk = kb + t * 4;
            int l = l0 + kk;
            Hd[kk][dd] = loadH(b, l, d0 + dd);
            He[kk][dd] = loadH(b, l, e0 + dd);
        }
        __syncthreads();
#pragma unroll 8
        for (int kk = 0; kk < 32; ++kk) {
            float a0 = Hd[kk][ty * 4 + 0];
            float a1 = Hd[kk][ty * 4 + 1];
            float a2 = Hd[kk][ty * 4 + 2];
            float a3 = Hd[kk][ty * 4 + 3];
            float4 w = *(float4*)&He[kk][tx * 4];
            acc[0][0] += a0 * w.x; acc[0][1] += a0 * w.y; acc[0][2] += a0 * w.z; acc[0][3] += a0 * w.w;
            acc[1][0] += a1 * w.x; acc[1][1] += a1 * w.y; acc[1][2] += a1 * w.z; acc[1][3] += a1 * w.w;
            acc[2][0] += a2 * w.x; acc[2][1] += a2 * w.y; acc[2][2] += a2 * w.z; acc[2][3] += a2 * w.w;
            acc[3][0] += a3 * w.x; acc[3][1] += a3 * w.y; acc[3][2] += a3 * w.z; acc[3][3] += a3 * w.w;
        }
    }

#pragma unroll
    for (int bi = 0; bi < 4; ++bi) {
        int dr = d0 + ty * 4 + bi;
        if (dr < 513) {
#pragma unroll
            for (int ni = 0; ni < 4; ++ni) {
                int e = e0 + tx * 4 + ni;
                if (e < 513)
                    g_HtH[(b * 513 + dr) * 520 + e] = acc[bi][ni];
            }
        }
    }
}

// ---------------------------------------------------------------------------
// Phase 2b: HtU[b][d] = sum_l Haug[b][l][d] * target[b][l]
// ---------------------------------------------------------------------------
__global__ __launch_bounds__(256) void htu_kernel(const float* __restrict__ x)
{
    const int b = (int)blockIdx.x;
    const int dcol = (int)blockIdx.y * 256 + (int)threadIdx.x;
    if (dcol >= 513) return;
    const float* __restrict__ xb = x + b * 4096;
    float acc = 0.f;
    if (dcol < 256) {
        for (int r = 0; r < 63; ++r)
            for (int c = 0; c < 63; ++c)
                acc += xb[(r + 1) * 64 + c + 1] *
                       g_state[(((r + 1) * 64 + c) * 64 + b) * 256 + dcol];
    } else if (dcol < 512) {
        const int d2 = dcol - 256;
        for (int r = 0; r < 63; ++r)
            for (int c = 0; c < 63; ++c)
                acc += xb[(r + 1) * 64 + c + 1] *
                       g_state[((r * 64 + (c + 1)) * 64 + b) * 256 + d2];
    } else {
        for (int r = 0; r < 63; ++r)
            for (int c = 0; c < 63; ++c)
                acc += xb[(r + 1) * 64 + c + 1];
    }
    g_HtU[b * 513 + dcol] = acc;
}

// ---------------------------------------------------------------------------
// Phase 3a: build augmented A = HtH + 25 I with RHS appended in column 513.
// Reads only the stored upper triangle of HtH via (min,max).
// ---------------------------------------------------------------------------
__global__ void prep_kernel()
{
    const int b = (int)blockIdx.x;
    const int r = (int)blockIdx.y;
    for (int c = (int)threadIdx.x; c < 514; c += (int)blockDim.x) {
        float v;
        if (c == 513) {
            v = g_HtU[b * 513 + r];
        } else {
            int dlo = r < c ? r : c;
            int dhi = r < c ? c : r;
            v = g_HtH[(b * 513 + dlo) * 520 + dhi];
            if (r == c) v += 25.0f;
        }
        g_A[(b * 513 + r) * 520 + c] = v;
    }
}

// ---------------------------------------------------------------------------
// Phase 3b: per-batch blocked LU (no pivoting; A SPD) + back substitution.
// One block per batch, 512 threads. Panel NB=16 in smem; rank-16 trailing
// updates with 2-row x 4-col register blocking. RHS carried as column 513.
// ---------------------------------------------------------------------------
__global__ __launch_bounds__(512) void solve_kernel(float* __restrict__ out)
{
    __shared__ float P[513 * 17];     // panel [row][17] (padded)
    __shared__ float Us[16 * 132];    // U rows chunk [kk][132] (padded)
    __shared__ float red[16];

    const int b = (int)blockIdx.x;
    const int tid = (int)threadIdx.x;
    float* __restrict__ A = g_A + b * 513 * 520;

    for (int k0 = 0; k0 < 513; k0 += 16) {
        const int nb = (513 - k0) < 16 ? (513 - k0) : 16;
        const int nrows = 513 - k0;

        // load panel (rows k0..512, cols k0..k0+nb)
        for (int idx = tid; idx < nrows * nb; idx += 512) {
            int rr = idx / nb, cc = idx - rr * nb;
            P[rr * 17 + cc] = A[(k0 + rr) * 520 + (k0 + cc)];
        }
        __syncthreads();

        // factor panel in smem
        for (int kk = 0; kk < nb; ++kk) {
            float inv = 1.0f / P[kk * 17 + kk];
            for (int rr = kk + 1 + tid; rr < nrows; rr += 512) {
                float lv = P[rr * 17 + kk] * inv;
                P[rr * 17 + kk] = lv;
                for (int cc = kk + 1; cc < nb; ++cc)
                    P[rr * 17 + cc] -= lv * P[kk * 17 + cc];
            }
            __syncthreads();
        }

        // write panel back
        for (int idx = tid; idx < nrows * nb; idx += 512) {
            int rr = idx / nb, cc = idx - rr * nb;
            A[(k0 + rr) * 520 + (k0 + cc)] = P[rr * 17 + cc];
        }
        __syncthreads();

        const int cstart = k0 + nb;
        const int width = 514 - cstart;   // includes RHS column 513
        for (int ch = 0; ch < width; ch += 128) {
            int wlen = width - ch; if (wlen > 128) wlen = 128;
            const int wlenp = (wlen + 3) & ~3;   // safe: ld=520 >= 517
            const int cbase = cstart + ch;

            // load the nb U rows for this column chunk
            for (int idx = tid; idx < nb * wlenp; idx += 512) {
                int rr = idx / wlenp, cc = idx - rr * wlenp;
                Us[rr * 132 + cc] = A[(k0 + rr) * 520 + cbase + cc];
            }
            __syncthreads();

            // triangular solve L_panel^{-1} * Urows (per-column ownership)
            for (int cc = tid; cc < wlenp; cc += 512) {
                float col[16];
                for (int m = 0; m < nb; ++m) col[m] = Us[m * 132 + cc];
                for (int kk = 1; kk < nb; ++kk) {
                    float v = col[kk];
                    for (int m = 0; m < kk; ++m) v -= P[kk * 17 + m] * col[m];
                    col[kk] = v;
                }
                for (int m = 0; m < nb; ++m) {
                    Us[m * 132 + cc] = col[m];
                    A[(k0 + m) * 520 + cbase + cc] = col[m];
                }
            }
            __syncthreads();

            // trailing update: A[r][c] -= sum_m L[r][m] * U[m][c]
            const int trows = nrows - nb;
            const int npr = (trows + 1) >> 1;
            const int ncq = wlenp >> 2;
            for (int idx = tid; idx < npr * ncq; idx += 512) {
                int pr = idx / ncq, cq = idx - pr * ncq;
                int row0 = cstart + pr * 2;
                int cc = cq * 4;
                bool has2 = (pr * 2 + 1) < trows;
                float4 a0 = *(float4*)&A[row0 * 520 + cbase + cc];
                float4 a1 = has2 ? *(float4*)&A[(row0 + 1) * 520 + cbase + cc] : a0;
                const float* P0 = &P[(row0 - k0) * 17];
                const float* P1 = has2 ? (P0 + 17) : P0;
#pragma unroll
                for (int m = 0; m < 16; ++m) {
                    if (m < nb) {
                        float4 u = *(float4*)&Us[m * 132 + cc];
                        float p0 = P0[m], p1 = P1[m];
                        a0.x -= p0 * u.x; a0.y -= p0 * u.y; a0.z -= p0 * u.z; a0.w -= p0 * u.w;
                        a1.x -= p1 * u.x; a1.y -= p1 * u.y; a1.z -= p1 * u.z; a1.w -= p1 * u.w;
                    }
                }
                *(float4*)&A[row0 * 520 + cbase + cc] = a0;
                if (has2) *(float4*)&A[(row0 + 1) * 520 + cbase + cc] = a1;
            }
            __syncthreads();
        }
    }

    // back substitution: U x = y  (y in column 513)
    float* xs = P;   // reuse panel smem
    const int lane = tid & 31, wid = tid >> 5;
    for (int r = 512; r >= 0; --r) {
        float part = 0.f;
        for (int c = r + 1 + tid; c <= 512; c += 512)
            part += A[r * 520 + c] * xs[c];
#pragma unroll
        for (int off = 16; off > 0; off >>= 1)
            part += __shfl_down_sync(0xffffffffu, part, off);
        if (lane == 0) red[wid] = part;
        __syncthreads();
        if (tid == 0) {
            float s = 0.f;
#pragma unroll
            for (int w2 = 0; w2 < 16; ++w2) s += red[w2];
            xs[r] = (A[r * 520 + 513] - s) / A[r * 520 + r];
        }
        __syncthreads();
    }
    for (int i2 = tid; i2 < 513; i2 += 512)
        out[b * 513 + i2] = xs[i2];
}

// ---------------------------------------------------------------------------
extern "C" void kernel_launch(void* const* d_in, const int* in_sizes, int n_in,
                              void* d_out, int out_size)
{
    const float* x   = (const float*)d_in[0];
    const float* Win = (const float*)d_in[1];
    const float* W1  = (const float*)d_in[2];
    const float* W2  = (const float*)d_in[3];
    float* out = (float*)d_out;

    for (int d = 0; d < 127; ++d) {
        int i_min = d > 63 ? d - 63 : 0;
        int i_max = d < 63 ? d : 63;
        dim3 grid(i_max - i_min + 1, 2, 2);
        scan_diag<<<grid, 256>>>(x, Win, W1, W2, d, i_min);
    }
    hth_kernel<<<dim3(45, 64), 256>>>();
    htu_kernel<<<dim3(64, 3), 256>>>(x);
    prep_kernel<<<dim3(64, 513), 256>>>();
    solve_kernel<<<64, 512>>>(out);
}

// round 2
// speedup vs baseline: 1.0872x; 1.0872x over previous
#include <cuda_runtime.h>

// Problem constants: B=64, H=64, W=64, n=256, NF=513, L=63*63=3969, alpha^2=25

__device__ float g_state[64 * 64 * 64 * 256];   // [cell=(i*64+j)][b][n]
__device__ float g_A[64 * 513 * 520];           // augmented [513 x 514] per batch, ld=520

// ---- packed f32x2 helpers (Blackwell dual fp32 pipe) -----------------------
__device__ __forceinline__ unsigned long long pk2(float a, float b) {
    unsigned long long r;
    asm("mov.b64 %0,{%1,%2};" : "=l"(r) : "f"(a), "f"(b));
    return r;
}
__device__ __forceinline__ void fma2(unsigned long long& d,
                                     unsigned long long a, unsigned long long b) {
    asm("fma.rn.f32x2 %0,%1,%2,%0;" : "+l"(d) : "l"(a), "l"(b));
}
__device__ __forceinline__ void unpk2(unsigned long long v, float& a, float& b) {
    asm("mov.b64 {%0,%1},%2;" : "=f"(a), "=f"(b) : "l"(v));
}

// ---------------------------------------------------------------------------
// Phase 1: wavefront scan.  One launch per anti-diagonal d = i+j.
// Block: 256 threads, 32 batches x 128 features of one cell. grid=(cells,2,2).
// Double-buffered smem staging; f32x2 inner loop (pairs over batch).
// ---------------------------------------------------------------------------
__global__ __launch_bounds__(256) void scan_diag(
    const float* __restrict__ x, const float* __restrict__ Win,
    const float* __restrict__ W1, const float* __restrict__ W2,
    int d, int i_min)
{
    __shared__ __align__(16) float in_s[2][32][34];   // [buf][k][b] (pad 34)
    __shared__ __align__(16) float w_s[2][32][128];   // [buf][k][n]

    const int i = i_min + (int)blockIdx.x;
    const int j = d - i;
    const int b0 = (int)blockIdx.y * 32;
    const int n0 = (int)blockIdx.z * 128;
    const int tid = (int)threadIdx.x;
    const int tx = tid & 31;    // n: 4 cols
    const int ty = tid >> 5;    // b: 4 rows (2 pairs)

    const bool hasL = (j > 0);
    const bool hasU = (i > 0);
    const int cellL = hasL ? ((i * 64 + (j - 1)) * 64) : 0;
    const int cellU = hasU ? (((i - 1) * 64 + j) * 64) : 0;

    const int bb = tid >> 3;   // 0..31 batch for input staging
    const int kq = tid & 7;    // 0..7  k-quad for input staging

    unsigned long long acc[2][4];
#pragma unroll
    for (int p = 0; p < 2; ++p)
#pragma unroll
        for (int c = 0; c < 4; ++c) acc[p][c] = 0ull;

    float4 inr;
    float4 wr[4];

    auto LOADC = [&](int kc) {
        const int k0 = kc * 32;
        const bool isLeft = (k0 < 256);
        const bool has = isLeft ? hasL : hasU;
        const int ks = isLeft ? k0 : (k0 - 256);
        inr = make_float4(0.f, 0.f, 0.f, 0.f);
        if (has) {
            const int cell = isLeft ? cellL : cellU;
            inr = *(const float4*)&g_state[(cell + b0 + bb) * 256 + ks + kq * 4];
        }
        const float* __restrict__ Wm = isLeft ? W1 : W2;
#pragma unroll
        for (int t = 0; t < 4; ++t) {
            int fi = tid + t * 256;
            int kl = fi >> 5;
            int cq = fi & 31;
            wr[t] = *(const float4*)&Wm[(ks + kl) * 256 + n0 + cq * 4];
        }
    };
    auto STOREC = [&](int buf) {
        in_s[buf][kq * 4 + 0][bb] = inr.x;
        in_s[buf][kq * 4 + 1][bb] = inr.y;
        in_s[buf][kq * 4 + 2][bb] = inr.z;
        in_s[buf][kq * 4 + 3][bb] = inr.w;
#pragma unroll
        for (int t = 0; t < 4; ++t) {
            int fi = tid + t * 256;
            int kl = fi >> 5;
            int cq = fi & 31;
            *(float4*)&w_s[buf][kl][cq * 4] = wr[t];
        }
    };

    LOADC(0);
    STOREC(0);

    for (int kc = 0; kc < 16; ++kc) {
        __syncthreads();
        if (kc < 15) LOADC(kc + 1);
        const int buf = kc & 1;
#pragma unroll 8
        for (int kl = 0; kl < 32; ++kl) {
            unsigned long long a01 = *(const unsigned long long*)&in_s[buf][kl][ty * 4];
            unsigned long long a23 = *(const unsigned long long*)&in_s[buf][kl][ty * 4 + 2];
            float4 w = *(const float4*)&w_s[buf][kl][tx * 4];
            unsigned long long wx = pk2(w.x, w.x);
            unsigned long long wy = pk2(w.y, w.y);
            unsigned long long wz = pk2(w.z, w.z);
            unsigned long long ww = pk2(w.w, w.w);
            fma2(acc[0][0], a01, wx); fma2(acc[0][1], a01, wy);
            fma2(acc[0][2], a01, wz); fma2(acc[0][3], a01, ww);
            fma2(acc[1][0], a23, wx); fma2(acc[1][1], a23, wy);
            fma2(acc[1][2], a23, wz); fma2(acc[1][3], a23, ww);
        }
        if (kc < 15) STOREC((kc + 1) & 1);
    }

    // epilogue: + x*Win, tanh, store
    const int cell = (i * 64 + j) * 64;
    float4 wv = *(const float4*)&Win[n0 + tx * 4];
#pragma unroll
    for (int p = 0; p < 2; ++p) {
        float lo0, hi0, lo1, hi1, lo2, hi2, lo3, hi3;
        unpk2(acc[p][0], lo0, hi0);
        unpk2(acc[p][1], lo1, hi1);
        unpk2(acc[p][2], lo2, hi2);
        unpk2(acc[p][3], lo3, hi3);
        const int bA = b0 + ty * 4 + 2 * p;
        const int bB = bA + 1;
        const float xA = x[(bA * 64 + i) * 64 + j];
        const float xB = x[(bB * 64 + i) * 64 + j];
        float4 oA, oB;
        oA.x = tanhf(lo0 + xA * wv.x); oA.y = tanhf(lo1 + xA * wv.y);
        oA.z = tanhf(lo2 + xA * wv.z); oA.w = tanhf(lo3 + xA * wv.w);
        oB.x = tanhf(hi0 + xB * wv.x); oB.y = tanhf(hi1 + xB * wv.y);
        oB.z = tanhf(hi2 + xB * wv.z); oB.w = tanhf(hi3 + xB * wv.w);
        *(float4*)&g_state[(cell + bA) * 256 + n0 + tx * 4] = oA;
        *(float4*)&g_state[(cell + bB) * 256 + n0 + tx * 4] = oB;
    }
}

// ---------------------------------------------------------------------------
// Phase 2a: HtH tiles -> write both triangles of A directly, += 25 on diagonal.
// Haug column d: d<256 -> state[r+1][c][b][d]; d<512 -> state[r][c+1][b][d-256];
// d==512 -> 1.   l = r*63 + c.
// grid = (45 tile-pairs, 64 batches), 256 threads, 64x64 tile, f32x2 4x4/thread.
// ---------------------------------------------------------------------------
__device__ __forceinline__ float loadH(int b, int l, int col) {
    if (l >= 3969) return 0.f;
    int r = l / 63;
    int c = l - r * 63;
    if (col < 256)
        return g_state[(((r + 1) * 64 + c) * 64 + b) * 256 + col];
    else if (col < 512)
        return g_state[((r * 64 + (c + 1)) * 64 + b) * 256 + (col - 256)];
    else
        return (col == 512) ? 1.f : 0.f;
}

__global__ __launch_bounds__(256) void hth_kernel()
{
    __shared__ __align__(16) float Hd[32][64];
    __shared__ __align__(16) float He[32][64];

    int rem = (int)blockIdx.x;
    int ti = 0;
    while (rem >= 9 - ti) { rem -= 9 - ti; ++ti; }
    const int tj = ti + rem;
    const int b = (int)blockIdx.y;
    const int d0 = ti * 64, e0 = tj * 64;

    const int tid = (int)threadIdx.x;
    const int tx = tid & 15, ty = tid >> 4;
    const int dd = tid & 63, kb = tid >> 6;

    unsigned long long acc[2][4];
#pragma unroll
    for (int p = 0; p < 2; ++p)
#pragma unroll
        for (int c = 0; c < 4; ++c) acc[p][c] = 0ull;

    for (int l0 = 0; l0 < 3969; l0 += 32) {
        __syncthreads();
#pragma unroll
        for (int t = 0; t < 8; ++t) {
            int kk = kb + t * 4;
            int l = l0 + kk;
            Hd[kk][dd] = loadH(b, l, d0 + dd);
            He[kk][dd] = loadH(b, l, e0 + dd);
        }
        __syncthreads();
#pragma unroll 8
        for (int kk = 0; kk < 32; ++kk) {
            unsigned long long a01 = *(const unsigned long long*)&Hd[kk][ty * 4];
            unsigned long long a23 = *(const unsigned long long*)&Hd[kk][ty * 4 + 2];
            float4 w = *(const float4*)&He[kk][tx * 4];
            unsigned long long wx = pk2(w.x, w.x);
            unsigned long long wy = pk2(w.y, w.y);
            unsigned long long wz = pk2(w.z, w.z);
            unsigned long long ww = pk2(w.w, w.w);
            fma2(acc[0][0], a01, wx); fma2(acc[0][1], a01, wy);
            fma2(acc[0][2], a01, wz); fma2(acc[0][3], a01, ww);
            fma2(acc[1][0], a23, wx); fma2(acc[1][1], a23, wy);
            fma2(acc[1][2], a23, wz); fma2(acc[1][3], a23, ww);
        }
    }

    float v[4][4];
#pragma unroll
    for (int p = 0; p < 2; ++p)
#pragma unroll
        for (int c = 0; c < 4; ++c)
            unpk2(acc[p][c], v[2 * p][c], v[2 * p + 1][c]);

    float* __restrict__ A = g_A + b * 513 * 520;
#pragma unroll
    for (int r = 0; r < 4; ++r) {
        int dr = d0 + ty * 4 + r;
        if (dr >= 513) continue;
#pragma unroll
        for (int c = 0; c < 4; ++c) {
            int e = e0 + tx * 4 + c;
            if (e >= 513) continue;
            float val = v[r][c];
            if (dr == e) val += 25.0f;
            A[dr * 520 + e] = val;
            if (ti != tj) A[e * 520 + dr] = val;
        }
    }
}

// ---------------------------------------------------------------------------
// Phase 2b: HtU -> column 513 of A.
// ---------------------------------------------------------------------------
__global__ __launch_bounds__(256) void htu_kernel(const float* __restrict__ x)
{
    const int b = (int)blockIdx.x;
    const int dcol = (int)blockIdx.y * 256 + (int)threadIdx.x;
    if (dcol >= 513) return;
    const float* __restrict__ xb = x + b * 4096;
    float acc = 0.f;
    if (dcol < 256) {
        for (int r = 0; r < 63; ++r)
            for (int c = 0; c < 63; ++c)
                acc += xb[(r + 1) * 64 + c + 1] *
                       g_state[(((r + 1) * 64 + c) * 64 + b) * 256 + dcol];
    } else if (dcol < 512) {
        const int d2 = dcol - 256;
        for (int r = 0; r < 63; ++r)
            for (int c = 0; c < 63; ++c)
                acc += xb[(r + 1) * 64 + c + 1] *
                       g_state[((r * 64 + (c + 1)) * 64 + b) * 256 + d2];
    } else {
        for (int r = 0; r < 63; ++r)
            for (int c = 0; c < 63; ++c)
                acc += xb[(r + 1) * 64 + c + 1];
    }
    g_A[(b * 513 + dcol) * 520 + 513] = acc;
}

// ---------------------------------------------------------------------------
// Phase 3: per-batch blocked LU (no pivoting; SPD) + back substitution.
// One block per batch, 512 threads. Trailing update uses f32x2.
// ---------------------------------------------------------------------------
__global__ __launch_bounds__(512) void solve_kernel(float* __restrict__ out)
{
    __shared__ float P[513 * 17];
    __shared__ __align__(16) float Us[16 * 132];
    __shared__ float red[16];

    const int b = (int)blockIdx.x;
    const int tid = (int)threadIdx.x;
    float* __restrict__ A = g_A + b * 513 * 520;

    for (int k0 = 0; k0 < 513; k0 += 16) {
        const int nb = (513 - k0) < 16 ? (513 - k0) : 16;
        const int nrows = 513 - k0;

        for (int idx = tid; idx < nrows * nb; idx += 512) {
            int rr = idx / nb, cc = idx - rr * nb;
            P[rr * 17 + cc] = A[(k0 + rr) * 520 + (k0 + cc)];
        }
        __syncthreads();

        for (int kk = 0; kk < nb; ++kk) {
            float inv = 1.0f / P[kk * 17 + kk];
            for (int rr = kk + 1 + tid; rr < nrows; rr += 512) {
                float lv = P[rr * 17 + kk] * inv;
                P[rr * 17 + kk] = lv;
                for (int cc = kk + 1; cc < nb; ++cc)
                    P[rr * 17 + cc] -= lv * P[kk * 17 + cc];
            }
            __syncthreads();
        }

        for (int idx = tid; idx < nrows * nb; idx += 512) {
            int rr = idx / nb, cc = idx - rr * nb;
            A[(k0 + rr) * 520 + (k0 + cc)] = P[rr * 17 + cc];
        }
        __syncthreads();

        const int cstart = k0 + nb;
        const int width = 514 - cstart;
        for (int ch = 0; ch < width; ch += 128) {
            int wlen = width - ch; if (wlen > 128) wlen = 128;
            const int wlenp = (wlen + 3) & ~3;
            const int cbase = cstart + ch;

            for (int idx = tid; idx < nb * wlenp; idx += 512) {
                int rr = idx / wlenp, cc = idx - rr * wlenp;
                Us[rr * 132 + cc] = A[(k0 + rr) * 520 + cbase + cc];
            }
            __syncthreads();

            for (int cc = tid; cc < wlenp; cc += 512) {
                float col[16];
                for (int m = 0; m < nb; ++m) col[m] = Us[m * 132 + cc];
                for (int kk = 1; kk < nb; ++kk) {
                    float v = col[kk];
                    for (int m = 0; m < kk; ++m) v -= P[kk * 17 + m] * col[m];
                    col[kk] = v;
                }
                for (int m = 0; m < nb; ++m) {
                    Us[m * 132 + cc] = col[m];
                    A[(k0 + m) * 520 + cbase + cc] = col[m];
                }
            }
            __syncthreads();

            const int trows = nrows - nb;
            const int npr = (trows + 1) >> 1;
            const int ncq = wlenp >> 2;
            for (int idx = tid; idx < npr * ncq; idx += 512) {
                int pr = idx / ncq, cq = idx - pr * ncq;
                int row0 = cstart + pr * 2;
                int cc = cq * 4;
                bool has2 = (pr * 2 + 1) < trows;
                const unsigned long long* pa0 =
                    (const unsigned long long*)&A[row0 * 520 + cbase + cc];
                const unsigned long long* pa1 =
                    (const unsigned long long*)&A[(row0 + 1) * 520 + cbase + cc];
                unsigned long long a00 = pa0[0], a01 = pa0[1];
                unsigned long long a10 = has2 ? pa1[0] : a00;
                unsigned long long a11 = has2 ? pa1[1] : a01;
                const float* P0 = &P[(row0 - k0) * 17];
                const float* P1 = has2 ? (P0 + 17) : P0;
#pragma unroll
                for (int m = 0; m < 16; ++m) {
                    if (m < nb) {
                        const unsigned long long* pu =
                            (const unsigned long long*)&Us[m * 132 + cc];
                        unsigned long long u01 = pu[0], u23 = pu[1];
                        float p0 = P0[m], p1 = P1[m];
                        unsigned long long np0 = pk2(-p0, -p0);
                        unsigned long long np1 = pk2(-p1, -p1);
                        fma2(a00, u01, np0); fma2(a01, u23, np0);
                        fma2(a10, u01, np1); fma2(a11, u23, np1);
                    }
                }
                unsigned long long* sa0 =
                    (unsigned long long*)&A[row0 * 520 + cbase + cc];
                sa0[0] = a00; sa0[1] = a01;
                if (has2) {
                    unsigned long long* sa1 =
                        (unsigned long long*)&A[(row0 + 1) * 520 + cbase + cc];
                    sa1[0] = a10; sa1[1] = a11;
                }
            }
            __syncthreads();
        }
    }

    // back substitution: U x = y  (y in column 513)
    float* xs = P;
    const int lane = tid & 31, wid = tid >> 5;
    for (int r = 512; r >= 0; --r) {
        float part = 0.f;
        for (int c = r + 1 + tid; c <= 512; c += 512)
            part += A[r * 520 + c] * xs[c];
#pragma unroll
        for (int off = 16; off > 0; off >>= 1)
            part += __shfl_down_sync(0xffffffffu, part, off);
        if (lane == 0) red[wid] = part;
        __syncthreads();
        if (tid == 0) {
            float s = 0.f;
#pragma unroll
            for (int w2 = 0; w2 < 16; ++w2) s += red[w2];
            xs[r] = (A[r * 520 + 513] - s) / A[r * 520 + r];
        }
        __syncthreads();
    }
    for (int i2 = tid; i2 < 513; i2 += 512)
        out[b * 513 + i2] = xs[i2];
}

// ---------------------------------------------------------------------------
extern "C" void kernel_launch(void* const* d_in, const int* in_sizes, int n_in,
                              void* d_out, int out_size)
{
    const float* x   = (const float*)d_in[0];
    const float* Win = (const float*)d_in[1];
    const float* W1  = (const float*)d_in[2];
    const float* W2  = (const float*)d_in[3];
    float* out = (float*)d_out;

    for (int d = 0; d < 127; ++d) {
        int i_min = d > 63 ? d - 63 : 0;
        int i_max = d < 63 ? d : 63;
        dim3 grid(i_max - i_min + 1, 2, 2);
        scan_diag<<<grid, 256>>>(x, Win, W1, W2, d, i_min);
    }
    hth_kernel<<<dim3(45, 64), 256>>>();
    htu_kernel<<<dim3(64, 3), 256>>>(x);
    solve_kernel<<<64, 512>>>(out);
}